// round 2
// baseline (speedup 1.0000x reference)
#include <cuda_runtime.h>
#include <cuda_bf16.h>

// LocalDeepRFMFull: D=1024, D_r=256, B=4 stages, G=8, Ng=128, P=40, N=4096 rows.
// One CTA per row; thread t owns Wi row r=t (80 floats, packed as 40 f32x2 pairs
// in regs). Sliding 5-chunk register window over x/z (4 LDS.128 per group),
// packed fma.rn.f32x2 math (40 FFMA2/group). h staged in 32-group smem chunks
// (+4 float row pad) for the packed Wo reduce.

typedef unsigned long long ull;

#define DD      1024
#define DRR     256
#define NSTAGE  4
#define TPB     256
#define GCHUNK  32
#define XSH_LEN 1064   // 16 wrap-pre + 1024 + 24 wrap/guard-post

__device__ __forceinline__ void fma2(ull& d, ull a, ull b, ull c) {
    asm("fma.rn.f32x2 %0, %1, %2, %3;" : "=l"(d) : "l"(a), "l"(b), "l"(c));
}
__device__ __forceinline__ float2 unpk(ull v) {
    float2 r;
    asm("mov.b64 {%0, %1}, %2;" : "=f"(r.x), "=f"(r.y) : "l"(v));
    return r;
}

// load one 8-float chunk (4 packed pairs) from smem
#define LOADC(dst, srcf) do {                                   \
    const ulonglong2* _p = (const ulonglong2*)(srcf);           \
    ulonglong2 _v0 = _p[0], _v1 = _p[1];                        \
    (dst)[0] = _v0.x; (dst)[1] = _v0.y;                         \
    (dst)[2] = _v1.x; (dst)[3] = _v1.y; } while (0)

#define FMX(S, J)                                               \
    fma2(a0, wx[4*(J)+0], xd[S][0], a0);                        \
    fma2(a1, wx[4*(J)+1], xd[S][1], a1);                        \
    fma2(a2, wx[4*(J)+2], xd[S][2], a2);                        \
    fma2(a3, wx[4*(J)+3], xd[S][3], a3);

#define FMZ(S, J)                                               \
    fma2(a0, wz[4*(J)+0], zd[S][0], a0);                        \
    fma2(a1, wz[4*(J)+1], zd[S][1], a1);                        \
    fma2(a2, wz[4*(J)+2], zd[S][2], a2);                        \
    fma2(a3, wz[4*(J)+3], zd[S][3], a3);

// one group: 40 fma2, slide-load the freed slot S0, tanh, store h
#define GROUP(S0, S1, S2, S3, S4, G) do {                       \
    ull a0 = 0, a1 = 0, a2 = 0, a3 = 0;                         \
    FMX(S0, 0) FMX(S1, 1) FMX(S2, 2) FMX(S3, 3) FMX(S4, 4)      \
    FMZ(S0, 0) FMZ(S1, 1) FMZ(S2, 2) FMZ(S3, 3) FMZ(S4, 4)      \
    LOADC(xd[S0], x_sh + 8*(G) + 40);                           \
    LOADC(zd[S0], z_sh + 8*(G) + 40);                           \
    float2 f0 = unpk(a0), f1 = unpk(a1), f2 = unpk(a2), f3 = unpk(a3); \
    float acc = ((f0.x+f0.y) + (f1.x+f1.y))                     \
              + ((f2.x+f2.y) + (f3.x+f3.y)) + bias;             \
    float ax = fabsf(acc);                                      \
    float e  = __expf(-2.0f * ax);                              \
    float th = __fdividef(1.0f - e, 1.0f + e);                  \
    th = copysignf(th, acc);                                    \
    h_s[(G) - gc][t] = th; } while (0)

__global__ void __launch_bounds__(TPB, 1)
rfm_kernel(const float* __restrict__ x,
           const float* __restrict__ Wi,
           const float* __restrict__ bi,
           const float* __restrict__ Wo,
           float* __restrict__ out)
{
    __shared__ __align__(16) float x_sh[XSH_LEN];
    __shared__ __align__(16) float z_sh[XSH_LEN];
    __shared__ __align__(16) float zn_s[DD];
    __shared__ __align__(16) float h_s[GCHUNK][DRR + 4];

    const int row = blockIdx.x;
    const int t   = threadIdx.x;

    // Shifted layout: x_sh[i] = x[(i-16) mod 1024], i in [0,1064).
    const float* xr = x + (size_t)row * DD;
    for (int i = t; i < XSH_LEN; i += TPB) {
        float v = xr[(i + (DD - 16)) & (DD - 1)];
        x_sh[i] = v;
        z_sh[i] = v;
    }
    __syncthreads();

    for (int s = 0; s < NSTAGE; ++s) {
        // Hoist Wi row r=t as packed pairs: wx (x-part), wz (z-part).
        ull wx[20], wz[20];
        const ulonglong2* wrow = (const ulonglong2*)(Wi + ((size_t)(s * DRR + t)) * 80);
        #pragma unroll
        for (int k = 0; k < 10; ++k) {
            ulonglong2 v = wrow[k];
            wx[2*k] = v.x; wx[2*k+1] = v.y;
        }
        #pragma unroll
        for (int k = 0; k < 10; ++k) {
            ulonglong2 v = wrow[10 + k];
            wz[2*k] = v.x; wz[2*k+1] = v.y;
        }
        const float bias = bi[s * DRR + t];
        const ulonglong2* wo2 = (const ulonglong2*)(Wo + ((size_t)(s * 8 + (t & 7))) * DRR);

        for (int gc = 0; gc < 128; gc += GCHUNK) {
            // ---- h phase: sliding register window over 32 groups ----
            ull xd[5][4], zd[5][4];
            #pragma unroll
            for (int j = 0; j < 5; ++j) {
                LOADC(xd[j], x_sh + 8*gc + 8*j);
                LOADC(zd[j], z_sh + 8*gc + 8*j);
            }
            for (int b = 0; b < 6; ++b) {
                const int g0 = gc + 5 * b;
                GROUP(0,1,2,3,4, g0 + 0);
                GROUP(1,2,3,4,0, g0 + 1);
                GROUP(2,3,4,0,1, g0 + 2);
                GROUP(3,4,0,1,2, g0 + 3);
                GROUP(4,0,1,2,3, g0 + 4);
            }
            GROUP(0,1,2,3,4, gc + 30);
            GROUP(1,2,3,4,0, gc + 31);
            __syncthreads();

            // ---- Z phase: thread t -> (group gl = t>>3, col c = t&7) ----
            {
                const int gl = t >> 3;
                const ulonglong2* h2 = (const ulonglong2*)&h_s[gl][0];
                ull s0 = 0, s1 = 0, s2 = 0, s3 = 0;
                #pragma unroll 4
                for (int k = 0; k < 32; ++k) {
                    ulonglong2 hva = h2[2*k],  hvb = h2[2*k+1];
                    ulonglong2 wva = wo2[2*k], wvb = wo2[2*k+1];
                    fma2(s0, hva.x, wva.x, s0);
                    fma2(s1, hva.y, wva.y, s1);
                    fma2(s2, hvb.x, wvb.x, s2);
                    fma2(s3, hvb.y, wvb.y, s3);
                }
                float2 f0 = unpk(s0), f1 = unpk(s1), f2 = unpk(s2), f3 = unpk(s3);
                zn_s[(gc << 3) + t] = ((f0.x+f0.y) + (f1.x+f1.y))
                                    + ((f2.x+f2.y) + (f3.x+f3.y));
            }
            __syncthreads();  // h_s reuse next chunk; orders zn_s at stage end
        }

        // z <- z_new in shifted layout (skip on last stage)
        if (s < NSTAGE - 1) {
            for (int i = t; i < XSH_LEN; i += TPB)
                z_sh[i] = zn_s[(i + (DD - 16)) & (DD - 1)];
            __syncthreads();
        }
    }

    float* orow = out + (size_t)row * DD;
    for (int j = t; j < DD; j += TPB) orow[j] = zn_s[j];
}

extern "C" void kernel_launch(void* const* d_in, const int* in_sizes, int n_in,
                              void* d_out, int out_size)
{
    const float* x  = (const float*)d_in[0];   // [4096, 1024]
    const float* Wi = (const float*)d_in[1];   // [4, 256, 80]
    const float* bi = (const float*)d_in[2];   // [4, 256]
    const float* Wo = (const float*)d_in[3];   // [4, 8, 256]
    float* out = (float*)d_out;                // [4096, 1024]

    const int nrows = in_sizes[0] / DD;
    rfm_kernel<<<nrows, TPB>>>(x, Wi, bi, Wo, out);
}

// round 4
// speedup vs baseline: 6.3003x; 6.3003x over previous
#include <cuda_runtime.h>
#include <cuda_bf16.h>

typedef unsigned int u32;
typedef unsigned short u16;

// LocalDeepRFMFull via warp-level bf16 MMA (mma.sync m16n8k16, plain sm_103 PTX).
// 2 batch rows per CTA (512 thr). Per stage: H = tanh(Y*Wi^T + bi) via split-bf16
// (3-pass cross terms), then Z = H*Wo^T via a second split-bf16 MMA (n=8).

#define TPB       512
#define NSTAGE    4
#define AB_STRIDE 336               // 160 bf16 cols + pad -> 21 x 16B (odd: conflict-free ldmatrix)
#define AB_BYTES  (256*AB_STRIDE)   // 86016
#define H_STRIDE  144               // 64 bf16 cols + pad -> 9 x 16B
#define H_BYTES   (256*H_STRIDE)    // 36864
#define WO_STRIDE 1040              // 512 bf16 cols + pad -> 65 x 16B
#define WO_BYTES  (8*WO_STRIDE)     // 8320
#define ZN_FLOATS 2048
#define BI_FLOATS 256
#define SMEM_TOTAL (2*AB_BYTES + H_BYTES + WO_BYTES + ZN_FLOATS*4 + BI_FLOATS*4) // 226432

// Prebuilt split-bf16 Wi images (cols 0..79 = hi, 80..159 = lo), row stride 336B.
__device__ __align__(16) unsigned char g_Bimg[NSTAGE][AB_BYTES];

__device__ __forceinline__ u32 smem_u32(const void* p) {
    u32 a;
    asm("{ .reg .u64 t; cvta.to.shared.u64 t, %1; cvt.u32.u64 %0, t; }" : "=r"(a) : "l"(p));
    return a;
}
// packs: low half = bf16(lo), high half = bf16(hi)
__device__ __forceinline__ u32 pack2(float lo, float hi) {
    u32 r; asm("cvt.rn.bf16x2.f32 %0, %1, %2;" : "=r"(r) : "f"(hi), "f"(lo)); return r;
}
__device__ __forceinline__ float tanhf_fast(float x) {
    float y; asm("tanh.approx.f32 %0, %1;" : "=f"(y) : "f"(x)); return y;
}

#define LDSM4(R0,R1,R2,R3,ADDR) \
    asm volatile("ldmatrix.sync.aligned.m8n8.x4.shared.b16 {%0,%1,%2,%3}, [%4];" \
        : "=r"(R0),"=r"(R1),"=r"(R2),"=r"(R3) : "r"(ADDR))
#define LDSM2(R0,R1,ADDR) \
    asm volatile("ldmatrix.sync.aligned.m8n8.x2.shared.b16 {%0,%1}, [%2];" \
        : "=r"(R0),"=r"(R1) : "r"(ADDR))
#define MMA(D,A0,A1,A2,A3,B0,B1) \
    asm volatile("mma.sync.aligned.m16n8k16.row.col.f32.bf16.bf16.f32 " \
        "{%0,%1,%2,%3}, {%4,%5,%6,%7}, {%8,%9}, {%0,%1,%2,%3};" \
        : "+f"((D)[0]),"+f"((D)[1]),"+f"((D)[2]),"+f"((D)[3]) \
        : "r"(A0),"r"(A1),"r"(A2),"r"(A3),"r"(B0),"r"(B1))

// ---------------- precompute: split-bf16 Wi images ----------------
__global__ void build_B_kernel(const float* __restrict__ Wi) {
    const int s = blockIdx.x, r = threadIdx.x;
    const float* w = Wi + (size_t)(s * 256 + r) * 80;
    unsigned char* img = g_Bimg[s] + r * AB_STRIDE;
    for (int c = 0; c < 80; c += 2) {
        float v0 = w[c], v1 = w[c + 1];
        u32 hp = pack2(v0, v1);
        float l0 = v0 - __uint_as_float(hp << 16);
        float l1 = v1 - __uint_as_float(hp & 0xFFFF0000u);
        u32 lp = pack2(l0, l1);
        *(u32*)(img + 2 * c)       = hp;  // hi cols c,c+1
        *(u32*)(img + 160 + 2 * c) = lp;  // lo cols 80+c,80+c+1
    }
}

// ---------------- main kernel ----------------
__global__ void __launch_bounds__(TPB, 1)
rfm_mma_kernel(const float* __restrict__ x, const float* __restrict__ bi,
               const float* __restrict__ Wo, float* __restrict__ out)
{
    extern __shared__ __align__(16) unsigned char smem[];
    unsigned char* A_sm  = smem;                 // 256 x 160 bf16: x_hi|z_hi|x_lo|z_lo
    unsigned char* B_sm  = smem + AB_BYTES;      // 256 x 160 bf16: Wi hi|lo
    unsigned char* H_sm  = smem + 2 * AB_BYTES;  // 256 x 64 bf16: h hi(32)|lo(32) per n-chunk
    unsigned char* WO_sm = H_sm + H_BYTES;       // 8 x 512 bf16: Wo hi(256)|lo(256)
    float* ZN = (float*)(WO_sm + WO_BYTES);      // [2][1024] fp32 z
    float* BI = ZN + ZN_FLOATS;                  // [256]

    const int t = threadIdx.x, w = t >> 5, lane = t & 31;
    const int rr = lane & 7, q = lane >> 3;

    const u32 A32 = smem_u32(A_sm), B32 = smem_u32(B_sm);
    const u32 H32 = smem_u32(H_sm), W32 = smem_u32(WO_sm);

    // per-thread ldmatrix base addresses (quad mappings)
    const u32 aT = A32 + (u32)((w * 16 + rr + 8 * (q & 1)) * AB_STRIDE + (q >> 1) * 16);
    const u32 bT = B32 + (u32)((rr + 8 * (q >> 1)) * AB_STRIDE + (q & 1) * 16);
    const u32 hT = H32 + (u32)((w * 16 + rr + 8 * (q & 1)) * H_STRIDE + (q >> 1) * 16);
    const u32 wT = W32 + (u32)(rr * WO_STRIDE + (q & 1) * 16);

    // ---- init A: x window -> x cols AND z cols (z starts = x) ----
    const float* xrow0 = x + (size_t)(2 * blockIdx.x) * 1024;
    for (int idx = t; idx < 256 * 20; idx += TPB) {
        int g = idx / 20, p = idx - g * 20;
        const float* xr = xrow0 + (g >> 7) * 1024;
        int basei = (8 * (g & 127) - 16 + 2 * p) & 1023;  // even -> pair never wraps
        float v0 = xr[basei], v1 = xr[basei + 1];
        u32 hp = pack2(v0, v1);
        float l0 = v0 - __uint_as_float(hp << 16);
        float l1 = v1 - __uint_as_float(hp & 0xFFFF0000u);
        u32 lp = pack2(l0, l1);
        unsigned char* arow = A_sm + g * AB_STRIDE;
        *(u32*)(arow + 4 * p)       = hp;   // x hi (cols 2p)
        *(u32*)(arow + 80 + 4 * p)  = hp;   // z hi (cols 40+2p)
        *(u32*)(arow + 160 + 4 * p) = lp;   // x lo (cols 80+2p)
        *(u32*)(arow + 240 + 4 * p) = lp;   // z lo (cols 120+2p)
    }

    for (int s = 0; s < NSTAGE; ++s) {
        // B image copy (L2-resident, shared by all CTAs)
        {
            const uint4* src = (const uint4*)(&g_Bimg[s][0]);
            uint4* dst = (uint4*)B_sm;
            for (int i = t; i < AB_BYTES / 16; i += TPB) dst[i] = src[i];
        }
        // Wo split build: hi at col r, lo at col 256+r
        for (int idx = t; idx < 2048; idx += TPB) {
            int c = idx >> 8, r = idx & 255;
            float f = Wo[(size_t)s * 2048 + c * 256 + r];
            u32 hp = pack2(f, 0.f);
            u16 hib = (u16)(hp & 0xFFFFu);
            float l = f - __uint_as_float((u32)hib << 16);
            u32 lp = pack2(l, 0.f);
            *(u16*)(WO_sm + c * WO_STRIDE + 2 * r)       = hib;
            *(u16*)(WO_sm + c * WO_STRIDE + 512 + 2 * r) = (u16)(lp & 0xFFFFu);
        }
        if (t < 256) BI[t] = bi[s * 256 + t];
        // A z-part from ZN (stages 1..3)
        if (s > 0) {
            for (int idx = t; idx < 256 * 20; idx += TPB) {
                int g = idx / 20, p = idx - g * 20;
                const float* zr = ZN + (g >> 7) * 1024;
                int basei = (8 * (g & 127) - 16 + 2 * p) & 1023;
                float v0 = zr[basei], v1 = zr[basei + 1];
                u32 hp = pack2(v0, v1);
                float l0 = v0 - __uint_as_float(hp << 16);
                float l1 = v1 - __uint_as_float(hp & 0xFFFF0000u);
                u32 lp = pack2(l0, l1);
                unsigned char* arow = A_sm + g * AB_STRIDE;
                *(u32*)(arow + 80 + 4 * p)  = hp;
                *(u32*)(arow + 240 + 4 * p) = lp;
            }
        }
        __syncthreads();

        float zacc[4] = {0.f, 0.f, 0.f, 0.f};

        for (int nc = 0; nc < 8; ++nc) {
            float d0[4] = {0,0,0,0}, d1[4] = {0,0,0,0}, d2[4] = {0,0,0,0}, d3[4] = {0,0,0,0};
            const u32 bBase = bT + (u32)(nc * 32 * AB_STRIDE);
            // 3-pass split: (Ahi,Bhi) (Alo,Bhi) (Ahi,Blo); col offsets in bf16 units
            static const int AKc[15] = {0,16,32,48,64, 80,96,112,128,144, 0,16,32,48,64};
            static const int BKc[15] = {0,16,32,48,64, 0,16,32,48,64, 80,96,112,128,144};
            #pragma unroll
            for (int ch = 0; ch < 15; ++ch) {
                u32 a0,a1,a2,a3, p0,p1,p2,p3, r0,r1,r2,r3;
                LDSM4(a0,a1,a2,a3, aT + AKc[ch] * 2);
                LDSM4(p0,p1,p2,p3, bBase + BKc[ch] * 2);
                LDSM4(r0,r1,r2,r3, bBase + 16 * AB_STRIDE + BKc[ch] * 2);
                MMA(d0, a0,a1,a2,a3, p0,p1);
                MMA(d1, a0,a1,a2,a3, p2,p3);
                MMA(d2, a0,a1,a2,a3, r0,r1);
                MMA(d3, a0,a1,a2,a3, r2,r3);
            }
            // ---- epilogue: +bias, tanh, split-bf16, store H ----
            {
                const int gA = w * 16 + (lane >> 2);
                #define EPI(D, J) do {                                              \
                    int lc = (J) * 8 + 2 * (lane & 3);                              \
                    float2 bp = *(const float2*)&BI[nc * 32 + lc];                  \
                    float h0 = tanhf_fast((D)[0] + bp.x);                           \
                    float h1 = tanhf_fast((D)[1] + bp.y);                           \
                    u32 hp = pack2(h0, h1);                                         \
                    float l0 = h0 - __uint_as_float(hp << 16);                      \
                    float l1 = h1 - __uint_as_float(hp & 0xFFFF0000u);              \
                    u32 lp = pack2(l0, l1);                                         \
                    *(u32*)(H_sm + gA * H_STRIDE + 2 * lc)      = hp;               \
                    *(u32*)(H_sm + gA * H_STRIDE + 64 + 2 * lc) = lp;               \
                    float h2 = tanhf_fast((D)[2] + bp.x);                           \
                    float h3 = tanhf_fast((D)[3] + bp.y);                           \
                    u32 hp2 = pack2(h2, h3);                                        \
                    float l2 = h2 - __uint_as_float(hp2 << 16);                     \
                    float l3 = h3 - __uint_as_float(hp2 & 0xFFFF0000u);             \
                    u32 lq = pack2(l2, l3);                                         \
                    *(u32*)(H_sm + (gA + 8) * H_STRIDE + 2 * lc)      = hp2;        \
                    *(u32*)(H_sm + (gA + 8) * H_STRIDE + 64 + 2 * lc) = lq;         \
                } while (0)
                EPI(d0, 0); EPI(d1, 1); EPI(d2, 2); EPI(d3, 3);
                #undef EPI
            }
            __syncthreads();
            // ---- z-gemm: Z += H(64k) * Wo^T, 3-pass split, n = 8 ----
            {
                static const int HKc[6] = {0, 16, 32, 48, 0, 16};
                const int wb = nc * 64;
                const int WBc[6] = {wb, wb + 32, wb, wb + 32, 512 + wb, 544 + wb};
                #pragma unroll
                for (int ch = 0; ch < 6; ++ch) {
                    u32 a0,a1,a2,a3,b0,b1;
                    LDSM4(a0,a1,a2,a3, hT + HKc[ch] * 2);
                    LDSM2(b0,b1, wT + WBc[ch]);
                    MMA(zacc, a0,a1,a2,a3, b0,b1);
                }
            }
            __syncthreads();   // H reuse guard for next nc
        }

        // ---- stage end: z frags -> ZN (or out) ----
        const int gA = w * 16 + (lane >> 2);
        const int c0 = 2 * (lane & 3);
        if (s < NSTAGE - 1) {
            *(float2*)&ZN[gA * 8 + c0]       = make_float2(zacc[0], zacc[1]);
            *(float2*)&ZN[(gA + 8) * 8 + c0] = make_float2(zacc[2], zacc[3]);
            __syncthreads();
        } else {
            float* orow = out + (size_t)(2 * blockIdx.x + (gA >> 7)) * 1024;
            *(float2*)&orow[(gA & 127) * 8 + c0]         = make_float2(zacc[0], zacc[1]);
            *(float2*)&orow[((gA + 8) & 127) * 8 + c0]   = make_float2(zacc[2], zacc[3]);
        }
    }
}

extern "C" void kernel_launch(void* const* d_in, const int* in_sizes, int n_in,
                              void* d_out, int out_size)
{
    const float* x  = (const float*)d_in[0];   // [4096, 1024]
    const float* Wi = (const float*)d_in[1];   // [4, 256, 80]
    const float* bi = (const float*)d_in[2];   // [4, 256]
    const float* Wo = (const float*)d_in[3];   // [4, 8, 256]
    float* out = (float*)d_out;                // [4096, 1024]

    cudaFuncSetAttribute(rfm_mma_kernel, cudaFuncAttributeMaxDynamicSharedMemorySize, SMEM_TOTAL);

    build_B_kernel<<<NSTAGE, 256>>>(Wi);
    const int nrows = in_sizes[0] / 1024;
    rfm_mma_kernel<<<nrows / 2, TPB, SMEM_TOTAL>>>(x, bi, Wo, out);
}

// round 5
// speedup vs baseline: 7.9867x; 1.2677x over previous
#include <cuda_runtime.h>
#include <cuda_bf16.h>

typedef unsigned int u32;
typedef unsigned short u16;

// LocalDeepRFMFull via mma.sync m16n8k16 bf16 (plain sm_103 PTX).
// 2 batch rows/CTA, 8 warps, m32 tile per warp. A-fragments hoisted in registers
// per stage. H never touches smem: D-frags -> tanh -> packed A-frags feed the
// z-GEMM directly (D-frag layout == A-frag layout after pairwise packing).

#define TPB       256
#define NSTAGE    4
#define AB_STRIDE 336               // 160 bf16 cols + pad -> 21 x 16B (conflict-free ldmatrix)
#define AB_BYTES  (256*AB_STRIDE)   // 86016
#define WO_STRIDE 1040              // 512 bf16 cols + pad -> 65 x 16B
#define WO_BYTES  (8*WO_STRIDE)     // 8320
#define SMEM_TOTAL (2*AB_BYTES + WO_BYTES + 2048*4 + 256*4)  // 189568

// Prebuilt split-bf16 Wi images (cols 0..79 = hi, 80..159 = lo), row stride 336B.
__device__ __align__(16) unsigned char g_Bimg[NSTAGE][AB_BYTES];

__device__ __forceinline__ u32 smem_u32(const void* p) {
    u32 a;
    asm("{ .reg .u64 t; cvta.to.shared.u64 t, %1; cvt.u32.u64 %0, t; }" : "=r"(a) : "l"(p));
    return a;
}
// packs: low half = bf16(lo), high half = bf16(hi)
__device__ __forceinline__ u32 pack2(float lo, float hi) {
    u32 r; asm("cvt.rn.bf16x2.f32 %0, %1, %2;" : "=r"(r) : "f"(hi), "f"(lo)); return r;
}
__device__ __forceinline__ float tanhf_fast(float x) {
    float y; asm("tanh.approx.f32 %0, %1;" : "=f"(y) : "f"(x)); return y;
}

#define LDSM4(R0,R1,R2,R3,ADDR) \
    asm volatile("ldmatrix.sync.aligned.m8n8.x4.shared.b16 {%0,%1,%2,%3}, [%4];" \
        : "=r"(R0),"=r"(R1),"=r"(R2),"=r"(R3) : "r"(ADDR))
#define LDSM2(R0,R1,ADDR) \
    asm volatile("ldmatrix.sync.aligned.m8n8.x2.shared.b16 {%0,%1}, [%2];" \
        : "=r"(R0),"=r"(R1) : "r"(ADDR))
#define MMA(D,A0,A1,A2,A3,B0,B1) \
    asm volatile("mma.sync.aligned.m16n8k16.row.col.f32.bf16.bf16.f32 " \
        "{%0,%1,%2,%3}, {%4,%5,%6,%7}, {%8,%9}, {%0,%1,%2,%3};" \
        : "+f"((D)[0]),"+f"((D)[1]),"+f"((D)[2]),"+f"((D)[3]) \
        : "r"(A0),"r"(A1),"r"(A2),"r"(A3),"r"(B0),"r"(B1))

// ---------------- precompute: split-bf16 Wi images ----------------
__global__ void build_B_kernel(const float* __restrict__ Wi) {
    const int s = blockIdx.x, r = threadIdx.x;
    const float* w = Wi + (size_t)(s * 256 + r) * 80;
    unsigned char* img = g_Bimg[s] + r * AB_STRIDE;
    for (int c = 0; c < 80; c += 2) {
        float v0 = w[c], v1 = w[c + 1];
        u32 hp = pack2(v0, v1);
        float l0 = v0 - __uint_as_float(hp << 16);
        float l1 = v1 - __uint_as_float(hp & 0xFFFF0000u);
        u32 lp = pack2(l0, l1);
        *(u32*)(img + 2 * c)       = hp;
        *(u32*)(img + 160 + 2 * c) = lp;
    }
}

// ---------------- main kernel ----------------
__global__ void __launch_bounds__(TPB, 1)
rfm_mma_kernel(const float* __restrict__ x, const float* __restrict__ bi,
               const float* __restrict__ Wo, float* __restrict__ out)
{
    extern __shared__ __align__(16) unsigned char smem[];
    unsigned char* A_sm  = smem;                 // 256 x 160 bf16: x_hi|z_hi|x_lo|z_lo
    unsigned char* B_sm  = smem + AB_BYTES;      // 256 x 160 bf16: Wi hi|lo
    unsigned char* WO_sm = smem + 2 * AB_BYTES;  // 8 x 512 bf16: Wo hi(256)|lo(256)
    float* ZN = (float*)(WO_sm + WO_BYTES);      // [2][1024] fp32 z
    float* BI = ZN + 2048;                       // [256]

    const int t = threadIdx.x, w = t >> 5, lane = t & 31;
    const int rr = lane & 7, q = lane >> 3;

    const u32 A32 = smem_u32(A_sm), B32 = smem_u32(B_sm), W32 = smem_u32(WO_sm);

    // ldmatrix thread base addresses
    const u32 aT = A32 + (u32)((32 * w + rr + 8 * (q & 1)) * AB_STRIDE + (q >> 1) * 16);
    const u32 bT = B32 + (u32)((rr + 8 * (q >> 1)) * AB_STRIDE + (q & 1) * 16);
    const u32 wT = W32 + (u32)(rr * WO_STRIDE + (q & 1) * 16);

    // ---- init A: x window -> x cols AND z cols (z starts = x) ----
    const float* xrow0 = x + (size_t)(2 * blockIdx.x) * 1024;
    for (int idx = t; idx < 256 * 20; idx += TPB) {
        int g = idx / 20, p = idx - g * 20;
        const float* xr = xrow0 + (g >> 7) * 1024;
        int basei = (8 * (g & 127) - 16 + 2 * p) & 1023;  // even -> pair never wraps
        float v0 = xr[basei], v1 = xr[basei + 1];
        u32 hp = pack2(v0, v1);
        float l0 = v0 - __uint_as_float(hp << 16);
        float l1 = v1 - __uint_as_float(hp & 0xFFFF0000u);
        u32 lp = pack2(l0, l1);
        unsigned char* arow = A_sm + g * AB_STRIDE;
        *(u32*)(arow + 4 * p)       = hp;   // x hi
        *(u32*)(arow + 80 + 4 * p)  = hp;   // z hi
        *(u32*)(arow + 160 + 4 * p) = lp;   // x lo
        *(u32*)(arow + 240 + 4 * p) = lp;   // z lo
    }

    for (int s = 0; s < NSTAGE; ++s) {
        // B image copy (L2-resident across CTAs)
        {
            const uint4* src = (const uint4*)(&g_Bimg[s][0]);
            uint4* dst = (uint4*)B_sm;
            for (int i = t; i < AB_BYTES / 16; i += TPB) dst[i] = src[i];
        }
        // Wo split: hi at byte 2r, lo at 512+2r (row = c)
        for (int idx = t; idx < 2048; idx += TPB) {
            int c = idx >> 8, r = idx & 255;
            float f = Wo[(size_t)s * 2048 + c * 256 + r];
            u32 hp = pack2(f, 0.f);
            u16 hib = (u16)(hp & 0xFFFFu);
            float l = f - __uint_as_float((u32)hib << 16);
            u32 lp = pack2(l, 0.f);
            *(u16*)(WO_sm + c * WO_STRIDE + 2 * r)       = hib;
            *(u16*)(WO_sm + c * WO_STRIDE + 512 + 2 * r) = (u16)(lp & 0xFFFFu);
        }
        if (t < 256) BI[t] = bi[s * 256 + t];
        // A z-cols from ZN (stages 1..3)
        if (s > 0) {
            for (int idx = t; idx < 256 * 20; idx += TPB) {
                int g = idx / 20, p = idx - g * 20;
                const float* zr = ZN + (g >> 7) * 1024;
                int basei = (8 * (g & 127) - 16 + 2 * p) & 1023;
                float v0 = zr[basei], v1 = zr[basei + 1];
                u32 hp = pack2(v0, v1);
                float l0 = v0 - __uint_as_float(hp << 16);
                float l1 = v1 - __uint_as_float(hp & 0xFFFF0000u);
                u32 lp = pack2(l0, l1);
                unsigned char* arow = A_sm + g * AB_STRIDE;
                *(u32*)(arow + 80 + 4 * p)  = hp;
                *(u32*)(arow + 240 + 4 * p) = lp;
            }
        }
        __syncthreads();

        // ---- hoist A fragments: 2 m16-tiles x 10 k16-chunks = 80 regs ----
        u32 A[2][10][4];
        #pragma unroll
        for (int mt = 0; mt < 2; ++mt)
            #pragma unroll
            for (int ch = 0; ch < 10; ++ch)
                LDSM4(A[mt][ch][0], A[mt][ch][1], A[mt][ch][2], A[mt][ch][3],
                      aT + (u32)(mt * 16 * AB_STRIDE + ch * 32));

        float zacc[2][4] = {{0,0,0,0},{0,0,0,0}};

        for (int nc = 0; nc < 8; ++nc) {
            float d[2][4][4] = {};
            const u32 bBase = bT + (u32)(nc * 32 * AB_STRIDE);

            // 15 k-chunks: (Ahi,Bhi) x5, (Alo,Bhi) x5, (Ahi,Blo) x5
            #pragma unroll
            for (int ch = 0; ch < 15; ++ch) {
                const int ai = (ch < 10) ? ch : ch - 10;
                const int bo = ((ch < 5) ? ch : ch - 5) * 32;
                u32 p0,p1,p2,p3, r0,r1,r2,r3;
                LDSM4(p0,p1,p2,p3, bBase + bo);
                LDSM4(r0,r1,r2,r3, bBase + 16 * AB_STRIDE + bo);
                #pragma unroll
                for (int mt = 0; mt < 2; ++mt) {
                    MMA(d[mt][0], A[mt][ai][0],A[mt][ai][1],A[mt][ai][2],A[mt][ai][3], p0,p1);
                    MMA(d[mt][1], A[mt][ai][0],A[mt][ai][1],A[mt][ai][2],A[mt][ai][3], p2,p3);
                    MMA(d[mt][2], A[mt][ai][0],A[mt][ai][1],A[mt][ai][2],A[mt][ai][3], r0,r1);
                    MMA(d[mt][3], A[mt][ai][0],A[mt][ai][1],A[mt][ai][2],A[mt][ai][3], r2,r3);
                }
            }

            // Wo fragments for this k-slice (r = nc*32..nc*32+31)
            u32 bh0a,bh0b,bh1a,bh1b, bl0a,bl0b,bl1a,bl1b;
            LDSM2(bh0a,bh0b, wT + (u32)(nc * 64));
            LDSM2(bh1a,bh1b, wT + (u32)(nc * 64 + 32));
            LDSM2(bl0a,bl0b, wT + (u32)(512 + nc * 64));
            LDSM2(bl1a,bl1b, wT + (u32)(512 + nc * 64 + 32));

            // ---- epilogue in registers: bias, tanh, split-bf16, z-MMA ----
            #pragma unroll
            for (int mt = 0; mt < 2; ++mt) {
                #pragma unroll
                for (int j = 0; j < 4; ++j) {
                    const int lc = nc * 32 + j * 8 + 2 * (lane & 3);
                    float2 bp = *(const float2*)&BI[lc];
                    d[mt][j][0] = tanhf_fast(d[mt][j][0] + bp.x);
                    d[mt][j][1] = tanhf_fast(d[mt][j][1] + bp.y);
                    d[mt][j][2] = tanhf_fast(d[mt][j][2] + bp.x);
                    d[mt][j][3] = tanhf_fast(d[mt][j][3] + bp.y);
                }
                u32 h[8], l[8];
                #pragma unroll
                for (int j = 0; j < 4; ++j) {
                    u32 hp0 = pack2(d[mt][j][0], d[mt][j][1]);
                    u32 hp1 = pack2(d[mt][j][2], d[mt][j][3]);
                    h[2*j] = hp0; h[2*j+1] = hp1;
                    float l0 = d[mt][j][0] - __uint_as_float(hp0 << 16);
                    float l1 = d[mt][j][1] - __uint_as_float(hp0 & 0xFFFF0000u);
                    float l2 = d[mt][j][2] - __uint_as_float(hp1 << 16);
                    float l3 = d[mt][j][3] - __uint_as_float(hp1 & 0xFFFF0000u);
                    l[2*j] = pack2(l0, l1); l[2*j+1] = pack2(l2, l3);
                }
                MMA(zacc[mt], h[0],h[1],h[2],h[3], bh0a,bh0b);
                MMA(zacc[mt], h[4],h[5],h[6],h[7], bh1a,bh1b);
                MMA(zacc[mt], l[0],l[1],l[2],l[3], bh0a,bh0b);
                MMA(zacc[mt], l[4],l[5],l[6],l[7], bh1a,bh1b);
                MMA(zacc[mt], h[0],h[1],h[2],h[3], bl0a,bl0b);
                MMA(zacc[mt], h[4],h[5],h[6],h[7], bl1a,bl1b);
            }
        }

        // ---- stage end: z frags -> ZN (or out) ----
        const int c0 = 2 * (lane & 3);
        if (s < NSTAGE - 1) {
            #pragma unroll
            for (int mt = 0; mt < 2; ++mt) {
                const int g = 32 * w + 16 * mt + (lane >> 2);
                *(float2*)&ZN[g * 8 + c0]       = make_float2(zacc[mt][0], zacc[mt][1]);
                *(float2*)&ZN[(g + 8) * 8 + c0] = make_float2(zacc[mt][2], zacc[mt][3]);
            }
            __syncthreads();   // ZN ready; also guards B_sm/WO_sm reuse next stage
        } else {
            #pragma unroll
            for (int mt = 0; mt < 2; ++mt) {
                const int g = 32 * w + 16 * mt + (lane >> 2);
                float* orow = out + (size_t)(2 * blockIdx.x + (g >> 7)) * 1024;
                *(float2*)&orow[(g & 127) * 8 + c0]       = make_float2(zacc[mt][0], zacc[mt][1]);
                *(float2*)&orow[((g + 8) & 127) * 8 + c0] = make_float2(zacc[mt][2], zacc[mt][3]);
            }
        }
    }
}

extern "C" void kernel_launch(void* const* d_in, const int* in_sizes, int n_in,
                              void* d_out, int out_size)
{
    const float* x  = (const float*)d_in[0];   // [4096, 1024]
    const float* Wi = (const float*)d_in[1];   // [4, 256, 80]
    const float* bi = (const float*)d_in[2];   // [4, 256]
    const float* Wo = (const float*)d_in[3];   // [4, 8, 256]
    float* out = (float*)d_out;                // [4096, 1024]

    cudaFuncSetAttribute(rfm_mma_kernel, cudaFuncAttributeMaxDynamicSharedMemorySize, SMEM_TOTAL);

    build_B_kernel<<<NSTAGE, 256>>>(Wi);
    const int nrows = in_sizes[0] / 1024;
    rfm_mma_kernel<<<nrows / 2, TPB, SMEM_TOTAL>>>(x, bi, Wo, out);
}

// round 6
// speedup vs baseline: 10.4654x; 1.3104x over previous
#include <cuda_runtime.h>
#include <cuda_fp16.h>

typedef unsigned int u32;
typedef unsigned short u16;

// LocalDeepRFMFull via mma.sync m16n8k16 fp16 (plain sm_103 PTX).
// 2 batch rows/CTA, 8 warps, m32 tile/warp. 2-pass fp16 split for the main GEMM
// (Ah*Bh + Al*Bh; residual = A*(B-Bh) ~ 2^-11), 3-pass for the tiny z-GEMM.
// A-fragments hoisted in registers; H never touches smem.

#define TPB       256
#define NSTAGE    4
#define A_STRIDE  336               // 160 fp16 cols + pad -> 21 x 16B (conflict-free ldmatrix)
#define A_BYTES   (256*A_STRIDE)    // 86016
#define B_STRIDE  176               // 80 fp16 cols + pad -> 11 x 16B
#define B_BYTES   (256*B_STRIDE)    // 45056
#define WO_STRIDE 1040              // 512 fp16 cols + pad -> 65 x 16B
#define WO_BYTES  (8*WO_STRIDE)     // 8320
#define SMEM_TOTAL (A_BYTES + B_BYTES + WO_BYTES + 2048*4 + 256*4)  // 148608

// Prebuilt fp16 Wi image (hi only, cols 0..79), row stride 176B.
__device__ __align__(16) unsigned char g_Bimg[NSTAGE][B_BYTES];

__device__ __forceinline__ u32 smem_u32(const void* p) {
    u32 a;
    asm("{ .reg .u64 t; cvta.to.shared.u64 t, %1; cvt.u32.u64 %0, t; }" : "=r"(a) : "l"(p));
    return a;
}
// pack: low half = fp16(lo), high half = fp16(hi)
__device__ __forceinline__ u32 pack2(float lo, float hi) {
    __half2 h = __floats2half2_rn(lo, hi);
    return *(u32*)&h;
}
__device__ __forceinline__ float lo_f(u32 p) { return __low2float(*(__half2*)&p); }
__device__ __forceinline__ float hi_f(u32 p) { return __high2float(*(__half2*)&p); }
__device__ __forceinline__ float tanhf_fast(float x) {
    float y; asm("tanh.approx.f32 %0, %1;" : "=f"(y) : "f"(x)); return y;
}

#define LDSM4(R0,R1,R2,R3,ADDR) \
    asm volatile("ldmatrix.sync.aligned.m8n8.x4.shared.b16 {%0,%1,%2,%3}, [%4];" \
        : "=r"(R0),"=r"(R1),"=r"(R2),"=r"(R3) : "r"(ADDR))
#define LDSM2(R0,R1,ADDR) \
    asm volatile("ldmatrix.sync.aligned.m8n8.x2.shared.b16 {%0,%1}, [%2];" \
        : "=r"(R0),"=r"(R1) : "r"(ADDR))
#define MMA(D,A0,A1,A2,A3,B0,B1) \
    asm volatile("mma.sync.aligned.m16n8k16.row.col.f32.f16.f16.f32 " \
        "{%0,%1,%2,%3}, {%4,%5,%6,%7}, {%8,%9}, {%0,%1,%2,%3};" \
        : "+f"((D)[0]),"+f"((D)[1]),"+f"((D)[2]),"+f"((D)[3]) \
        : "r"(A0),"r"(A1),"r"(A2),"r"(A3),"r"(B0),"r"(B1))

// ---------------- precompute: fp16 Wi image (hi only) ----------------
__global__ void build_B_kernel(const float* __restrict__ Wi) {
    const int s = blockIdx.x, r = threadIdx.x;
    const float* w = Wi + (size_t)(s * 256 + r) * 80;
    unsigned char* img = g_Bimg[s] + r * B_STRIDE;
    for (int c = 0; c < 80; c += 2)
        *(u32*)(img + 2 * c) = pack2(w[c], w[c + 1]);
}

// ---------------- main kernel ----------------
__global__ void __launch_bounds__(TPB, 1)
rfm_mma_kernel(const float* __restrict__ x, const float* __restrict__ bi,
               const float* __restrict__ Wo, float* __restrict__ out)
{
    extern __shared__ __align__(16) unsigned char smem[];
    unsigned char* A_sm  = smem;                       // 256 x 160 fp16: xh|zh|xl|zl
    unsigned char* B_sm  = smem + A_BYTES;             // 256 x 80 fp16: Wi hi
    unsigned char* WO_sm = smem + A_BYTES + B_BYTES;   // 8 x 512 fp16: Wo hi(256)|lo(256)
    float* ZN = (float*)(WO_sm + WO_BYTES);            // [2][1024] fp32 z
    float* BI = ZN + 2048;                             // [256]

    const int t = threadIdx.x, w = t >> 5, lane = t & 31;
    const int rr = lane & 7, q = lane >> 3;

    const u32 A32 = smem_u32(A_sm), B32 = smem_u32(B_sm), W32 = smem_u32(WO_sm);

    const u32 aT = A32 + (u32)((32 * w + rr + 8 * (q & 1)) * A_STRIDE + (q >> 1) * 16);
    const u32 bT = B32 + (u32)((rr + 8 * (q >> 1)) * B_STRIDE + (q & 1) * 16);
    const u32 wT = W32 + (u32)(rr * WO_STRIDE + (q & 1) * 16);

    // ---- init A: x window -> xh/xl AND zh/zl (z starts = x) ----
    const float* xrow0 = x + (size_t)(2 * blockIdx.x) * 1024;
    for (int idx = t; idx < 256 * 20; idx += TPB) {
        int g = idx / 20, p = idx - g * 20;
        const float* xr = xrow0 + (g >> 7) * 1024;
        int basei = (8 * (g & 127) - 16 + 2 * p) & 1023;  // even -> pair never wraps
        float v0 = xr[basei], v1 = xr[basei + 1];
        u32 hp = pack2(v0, v1);
        u32 lp = pack2(v0 - lo_f(hp), v1 - hi_f(hp));
        unsigned char* arow = A_sm + g * A_STRIDE;
        *(u32*)(arow + 4 * p)       = hp;   // x hi (cols 2p)
        *(u32*)(arow + 80 + 4 * p)  = hp;   // z hi (cols 40+2p)
        *(u32*)(arow + 160 + 4 * p) = lp;   // x lo (cols 80+2p)
        *(u32*)(arow + 240 + 4 * p) = lp;   // z lo (cols 120+2p)
    }

    for (int s = 0; s < NSTAGE; ++s) {
        // B image copy (L2-resident across CTAs)
        {
            const uint4* src = (const uint4*)(&g_Bimg[s][0]);
            uint4* dst = (uint4*)B_sm;
            for (int i = t; i < B_BYTES / 16; i += TPB) dst[i] = src[i];
        }
        // Wo split (fp16 hi + fp16 lo): hi at byte 2r, lo at 512+2r (row = c)
        for (int idx = t; idx < 2048; idx += TPB) {
            int c = idx >> 8, r = idx & 255;
            float f = Wo[(size_t)s * 2048 + c * 256 + r];
            __half hh = __float2half_rn(f);
            float l = f - __half2float(hh);
            __half hl = __float2half_rn(l);
            *(u16*)(WO_sm + c * WO_STRIDE + 2 * r)       = *(u16*)&hh;
            *(u16*)(WO_sm + c * WO_STRIDE + 512 + 2 * r) = *(u16*)&hl;
        }
        if (t < 256) BI[t] = bi[s * 256 + t];
        // A z-cols from ZN (stages 1..3)
        if (s > 0) {
            for (int idx = t; idx < 256 * 20; idx += TPB) {
                int g = idx / 20, p = idx - g * 20;
                const float* zr = ZN + (g >> 7) * 1024;
                int basei = (8 * (g & 127) - 16 + 2 * p) & 1023;
                float v0 = zr[basei], v1 = zr[basei + 1];
                u32 hp = pack2(v0, v1);
                u32 lp = pack2(v0 - lo_f(hp), v1 - hi_f(hp));
                unsigned char* arow = A_sm + g * A_STRIDE;
                *(u32*)(arow + 80 + 4 * p)  = hp;
                *(u32*)(arow + 240 + 4 * p) = lp;
            }
        }
        __syncthreads();

        // ---- hoist A fragments: 2 mt x {hi,lo} x 5 k16-chunks = 80 regs ----
        u32 A[2][2][5][4];
        #pragma unroll
        for (int mt = 0; mt < 2; ++mt)
            #pragma unroll
            for (int ch = 0; ch < 5; ++ch) {
                LDSM4(A[mt][0][ch][0], A[mt][0][ch][1], A[mt][0][ch][2], A[mt][0][ch][3],
                      aT + (u32)(mt * 16 * A_STRIDE + ch * 32));
                LDSM4(A[mt][1][ch][0], A[mt][1][ch][1], A[mt][1][ch][2], A[mt][1][ch][3],
                      aT + (u32)(mt * 16 * A_STRIDE + 160 + ch * 32));
            }

        float zacc[2][4] = {{0,0,0,0},{0,0,0,0}};

        for (int nc = 0; nc < 8; ++nc) {
            float d[2][4][4] = {};
            const u32 bBase = bT + (u32)(nc * 32 * B_STRIDE);

            // 5 k16-chunks; each Bh fragment reused by the Ah and Al passes
            #pragma unroll
            for (int ch = 0; ch < 5; ++ch) {
                u32 p0,p1,p2,p3, r0,r1,r2,r3;
                LDSM4(p0,p1,p2,p3, bBase + ch * 32);
                LDSM4(r0,r1,r2,r3, bBase + 16 * B_STRIDE + ch * 32);
                #pragma unroll
                for (int mt = 0; mt < 2; ++mt) {
                    MMA(d[mt][0], A[mt][0][ch][0],A[mt][0][ch][1],A[mt][0][ch][2],A[mt][0][ch][3], p0,p1);
                    MMA(d[mt][1], A[mt][0][ch][0],A[mt][0][ch][1],A[mt][0][ch][2],A[mt][0][ch][3], p2,p3);
                    MMA(d[mt][2], A[mt][0][ch][0],A[mt][0][ch][1],A[mt][0][ch][2],A[mt][0][ch][3], r0,r1);
                    MMA(d[mt][3], A[mt][0][ch][0],A[mt][0][ch][1],A[mt][0][ch][2],A[mt][0][ch][3], r2,r3);
                }
                #pragma unroll
                for (int mt = 0; mt < 2; ++mt) {
                    MMA(d[mt][0], A[mt][1][ch][0],A[mt][1][ch][1],A[mt][1][ch][2],A[mt][1][ch][3], p0,p1);
                    MMA(d[mt][1], A[mt][1][ch][0],A[mt][1][ch][1],A[mt][1][ch][2],A[mt][1][ch][3], p2,p3);
                    MMA(d[mt][2], A[mt][1][ch][0],A[mt][1][ch][1],A[mt][1][ch][2],A[mt][1][ch][3], r0,r1);
                    MMA(d[mt][3], A[mt][1][ch][0],A[mt][1][ch][1],A[mt][1][ch][2],A[mt][1][ch][3], r2,r3);
                }
            }

            // Wo fragments for this k-slice (r = nc*32..nc*32+31)
            u32 bh0a,bh0b,bh1a,bh1b, bl0a,bl0b,bl1a,bl1b;
            LDSM2(bh0a,bh0b, wT + (u32)(nc * 64));
            LDSM2(bh1a,bh1b, wT + (u32)(nc * 64 + 32));
            LDSM2(bl0a,bl0b, wT + (u32)(512 + nc * 64));
            LDSM2(bl1a,bl1b, wT + (u32)(512 + nc * 64 + 32));

            // ---- epilogue in registers: bias, tanh, fp16 split, z-MMA (3-pass) ----
            #pragma unroll
            for (int mt = 0; mt < 2; ++mt) {
                #pragma unroll
                for (int j = 0; j < 4; ++j) {
                    const int lc = nc * 32 + j * 8 + 2 * (lane & 3);
                    float2 bp = *(const float2*)&BI[lc];
                    d[mt][j][0] = tanhf_fast(d[mt][j][0] + bp.x);
                    d[mt][j][1] = tanhf_fast(d[mt][j][1] + bp.y);
                    d[mt][j][2] = tanhf_fast(d[mt][j][2] + bp.x);
                    d[mt][j][3] = tanhf_fast(d[mt][j][3] + bp.y);
                }
                u32 h[8], l[8];
                #pragma unroll
                for (int j = 0; j < 4; ++j) {
                    u32 hp0 = pack2(d[mt][j][0], d[mt][j][1]);
                    u32 hp1 = pack2(d[mt][j][2], d[mt][j][3]);
                    h[2*j] = hp0; h[2*j+1] = hp1;
                    l[2*j]   = pack2(d[mt][j][0] - lo_f(hp0), d[mt][j][1] - hi_f(hp0));
                    l[2*j+1] = pack2(d[mt][j][2] - lo_f(hp1), d[mt][j][3] - hi_f(hp1));
                }
                MMA(zacc[mt], h[0],h[1],h[2],h[3], bh0a,bh0b);
                MMA(zacc[mt], h[4],h[5],h[6],h[7], bh1a,bh1b);
                MMA(zacc[mt], l[0],l[1],l[2],l[3], bh0a,bh0b);
                MMA(zacc[mt], l[4],l[5],l[6],l[7], bh1a,bh1b);
                MMA(zacc[mt], h[0],h[1],h[2],h[3], bl0a,bl0b);
                MMA(zacc[mt], h[4],h[5],h[6],h[7], bl1a,bl1b);
            }
        }

        // ---- stage end: z frags -> ZN (or out) ----
        const int c0 = 2 * (lane & 3);
        if (s < NSTAGE - 1) {
            #pragma unroll
            for (int mt = 0; mt < 2; ++mt) {
                const int g = 32 * w + 16 * mt + (lane >> 2);
                *(float2*)&ZN[g * 8 + c0]       = make_float2(zacc[mt][0], zacc[mt][1]);
                *(float2*)&ZN[(g + 8) * 8 + c0] = make_float2(zacc[mt][2], zacc[mt][3]);
            }
            __syncthreads();   // ZN ready; also guards B_sm/WO_sm reuse next stage
        } else {
            #pragma unroll
            for (int mt = 0; mt < 2; ++mt) {
                const int g = 32 * w + 16 * mt + (lane >> 2);
                float* orow = out + (size_t)(2 * blockIdx.x + (g >> 7)) * 1024;
                *(float2*)&orow[(g & 127) * 8 + c0]       = make_float2(zacc[mt][0], zacc[mt][1]);
                *(float2*)&orow[((g + 8) & 127) * 8 + c0] = make_float2(zacc[mt][2], zacc[mt][3]);
            }
        }
    }
}

extern "C" void kernel_launch(void* const* d_in, const int* in_sizes, int n_in,
                              void* d_out, int out_size)
{
    const float* x  = (const float*)d_in[0];   // [4096, 1024]
    const float* Wi = (const float*)d_in[1];   // [4, 256, 80]
    const float* bi = (const float*)d_in[2];   // [4, 256]
    const float* Wo = (const float*)d_in[3];   // [4, 8, 256]
    float* out = (float*)d_out;                // [4096, 1024]

    cudaFuncSetAttribute(rfm_mma_kernel, cudaFuncAttributeMaxDynamicSharedMemorySize, SMEM_TOTAL);

    build_B_kernel<<<NSTAGE, 256>>>(Wi);
    const int nrows = in_sizes[0] / 1024;
    rfm_mma_kernel<<<nrows / 2, TPB, SMEM_TOTAL>>>(x, bi, Wo, out);
}

// round 7
// speedup vs baseline: 10.7180x; 1.0241x over previous
#include <cuda_runtime.h>
#include <cuda_fp16.h>

typedef unsigned int u32;
typedef unsigned short u16;

// LocalDeepRFMFull via mma.sync m16n8k16 fp16 (plain sm_103 PTX).
// 2 batch rows/CTA, 16 warps, m16 tile/warp (4 warps/SMSP for latency hiding).
// 2-pass fp16 split main GEMM (Ah*Bh + Al*Bh), 3-pass tiny z-GEMM.
// A-fragments hoisted in registers; H never touches smem.

#define TPB       512
#define NSTAGE    4
#define A_STRIDE  336               // 160 fp16 cols + pad -> 21 x 16B (conflict-free ldmatrix)
#define A_BYTES   (256*A_STRIDE)    // 86016
#define B_STRIDE  176               // 80 fp16 cols + pad -> 11 x 16B
#define B_BYTES   (256*B_STRIDE)    // 45056
#define WO_STRIDE 1040              // 512 fp16 cols + pad -> 65 x 16B
#define WO_BYTES  (8*WO_STRIDE)     // 8320
#define SMEM_TOTAL (A_BYTES + B_BYTES + WO_BYTES + 2048*4 + 256*4)  // 148608

// Prebuilt fp16 Wi image (cols 0..79), row stride 176B.
__device__ __align__(16) unsigned char g_Bimg[NSTAGE][B_BYTES];

__device__ __forceinline__ u32 smem_u32(const void* p) {
    u32 a;
    asm("{ .reg .u64 t; cvta.to.shared.u64 t, %1; cvt.u32.u64 %0, t; }" : "=r"(a) : "l"(p));
    return a;
}
// pack: low half = fp16(lo), high half = fp16(hi)
__device__ __forceinline__ u32 pack2(float lo, float hi) {
    __half2 h = __floats2half2_rn(lo, hi);
    return *(u32*)&h;
}
__device__ __forceinline__ float lo_f(u32 p) { return __low2float(*(__half2*)&p); }
__device__ __forceinline__ float hi_f(u32 p) { return __high2float(*(__half2*)&p); }
__device__ __forceinline__ float tanhf_fast(float x) {
    float y; asm("tanh.approx.f32 %0, %1;" : "=f"(y) : "f"(x)); return y;
}

#define LDSM4(R0,R1,R2,R3,ADDR) \
    asm volatile("ldmatrix.sync.aligned.m8n8.x4.shared.b16 {%0,%1,%2,%3}, [%4];" \
        : "=r"(R0),"=r"(R1),"=r"(R2),"=r"(R3) : "r"(ADDR))
#define LDSM2(R0,R1,ADDR) \
    asm volatile("ldmatrix.sync.aligned.m8n8.x2.shared.b16 {%0,%1}, [%2];" \
        : "=r"(R0),"=r"(R1) : "r"(ADDR))
#define MMA(D,A0,A1,A2,A3,B0,B1) \
    asm volatile("mma.sync.aligned.m16n8k16.row.col.f32.f16.f16.f32 " \
        "{%0,%1,%2,%3}, {%4,%5,%6,%7}, {%8,%9}, {%0,%1,%2,%3};" \
        : "+f"((D)[0]),"+f"((D)[1]),"+f"((D)[2]),"+f"((D)[3]) \
        : "r"(A0),"r"(A1),"r"(A2),"r"(A3),"r"(B0),"r"(B1))

// ---------------- precompute: fp16 Wi image (hi only) ----------------
__global__ void build_B_kernel(const float* __restrict__ Wi) {
    const int s = blockIdx.x, r = threadIdx.x;
    const float* w = Wi + (size_t)(s * 256 + r) * 80;
    unsigned char* img = g_Bimg[s] + r * B_STRIDE;
    for (int c = 0; c < 80; c += 2)
        *(u32*)(img + 2 * c) = pack2(w[c], w[c + 1]);
}

// ---------------- main kernel ----------------
__global__ void __launch_bounds__(TPB, 1)
rfm_mma_kernel(const float* __restrict__ x, const float* __restrict__ bi,
               const float* __restrict__ Wo, float* __restrict__ out)
{
    extern __shared__ __align__(16) unsigned char smem[];
    unsigned char* A_sm  = smem;                       // 256 x 160 fp16: xh|zh|xl|zl
    unsigned char* B_sm  = smem + A_BYTES;             // 256 x 80 fp16: Wi hi
    unsigned char* WO_sm = smem + A_BYTES + B_BYTES;   // 8 x 512 fp16: Wo hi(256)|lo(256)
    float* ZN = (float*)(WO_sm + WO_BYTES);            // [2][1024] fp32 z
    float* BI = ZN + 2048;                             // [256]

    const int t = threadIdx.x, w = t >> 5, lane = t & 31;
    const int rr = lane & 7, q = lane >> 3;

    const u32 A32 = smem_u32(A_sm), B32 = smem_u32(B_sm), W32 = smem_u32(WO_sm);

    // m16 tile per warp: rows 16w..16w+15
    const u32 aT = A32 + (u32)((16 * w + rr + 8 * (q & 1)) * A_STRIDE + (q >> 1) * 16);
    const u32 bT = B32 + (u32)((rr + 8 * (q >> 1)) * B_STRIDE + (q & 1) * 16);
    const u32 wT = W32 + (u32)(rr * WO_STRIDE + (q & 1) * 16);

    // ---- init A: x window -> xh/xl AND zh/zl (z starts = x) ----
    const float* xrow0 = x + (size_t)(2 * blockIdx.x) * 1024;
    for (int idx = t; idx < 256 * 20; idx += TPB) {
        int g = idx / 20, p = idx - g * 20;
        const float* xr = xrow0 + (g >> 7) * 1024;
        int basei = (8 * (g & 127) - 16 + 2 * p) & 1023;  // even -> pair never wraps
        float v0 = xr[basei], v1 = xr[basei + 1];
        u32 hp = pack2(v0, v1);
        u32 lp = pack2(v0 - lo_f(hp), v1 - hi_f(hp));
        unsigned char* arow = A_sm + g * A_STRIDE;
        *(u32*)(arow + 4 * p)       = hp;   // x hi (cols 2p)
        *(u32*)(arow + 80 + 4 * p)  = hp;   // z hi (cols 40+2p)
        *(u32*)(arow + 160 + 4 * p) = lp;   // x lo (cols 80+2p)
        *(u32*)(arow + 240 + 4 * p) = lp;   // z lo (cols 120+2p)
    }

    for (int s = 0; s < NSTAGE; ++s) {
        // B image copy (L2-resident across CTAs)
        {
            const uint4* src = (const uint4*)(&g_Bimg[s][0]);
            uint4* dst = (uint4*)B_sm;
            for (int i = t; i < B_BYTES / 16; i += TPB) dst[i] = src[i];
        }
        // Wo split (fp16 hi + lo): hi at byte 2r, lo at 512+2r (row = c)
        for (int idx = t; idx < 2048; idx += TPB) {
            int c = idx >> 8, r = idx & 255;
            float f = Wo[(size_t)s * 2048 + c * 256 + r];
            __half hh = __float2half_rn(f);
            float l = f - __half2float(hh);
            __half hl = __float2half_rn(l);
            *(u16*)(WO_sm + c * WO_STRIDE + 2 * r)       = *(u16*)&hh;
            *(u16*)(WO_sm + c * WO_STRIDE + 512 + 2 * r) = *(u16*)&hl;
        }
        if (t < 256) BI[t] = bi[s * 256 + t];
        // A z-cols from ZN (stages 1..3)
        if (s > 0) {
            for (int idx = t; idx < 256 * 20; idx += TPB) {
                int g = idx / 20, p = idx - g * 20;
                const float* zr = ZN + (g >> 7) * 1024;
                int basei = (8 * (g & 127) - 16 + 2 * p) & 1023;
                float v0 = zr[basei], v1 = zr[basei + 1];
                u32 hp = pack2(v0, v1);
                u32 lp = pack2(v0 - lo_f(hp), v1 - hi_f(hp));
                unsigned char* arow = A_sm + g * A_STRIDE;
                *(u32*)(arow + 80 + 4 * p)  = hp;
                *(u32*)(arow + 240 + 4 * p) = lp;
            }
        }
        __syncthreads();

        // ---- hoist A fragments: {hi,lo} x 5 k16-chunks = 40 regs ----
        u32 A[2][5][4];
        #pragma unroll
        for (int ch = 0; ch < 5; ++ch) {
            LDSM4(A[0][ch][0], A[0][ch][1], A[0][ch][2], A[0][ch][3],
                  aT + (u32)(ch * 32));
            LDSM4(A[1][ch][0], A[1][ch][1], A[1][ch][2], A[1][ch][3],
                  aT + (u32)(160 + ch * 32));
        }

        float zacc[4] = {0, 0, 0, 0};

        for (int nc = 0; nc < 8; ++nc) {
            float d[4][4] = {};
            const u32 bBase = bT + (u32)(nc * 32 * B_STRIDE);

            // 5 k16-chunks; each Bh fragment reused by the Ah and Al passes
            #pragma unroll
            for (int ch = 0; ch < 5; ++ch) {
                u32 p0,p1,p2,p3, r0,r1,r2,r3;
                LDSM4(p0,p1,p2,p3, bBase + ch * 32);
                LDSM4(r0,r1,r2,r3, bBase + 16 * B_STRIDE + ch * 32);
                MMA(d[0], A[0][ch][0],A[0][ch][1],A[0][ch][2],A[0][ch][3], p0,p1);
                MMA(d[1], A[0][ch][0],A[0][ch][1],A[0][ch][2],A[0][ch][3], p2,p3);
                MMA(d[2], A[0][ch][0],A[0][ch][1],A[0][ch][2],A[0][ch][3], r0,r1);
                MMA(d[3], A[0][ch][0],A[0][ch][1],A[0][ch][2],A[0][ch][3], r2,r3);
                MMA(d[0], A[1][ch][0],A[1][ch][1],A[1][ch][2],A[1][ch][3], p0,p1);
                MMA(d[1], A[1][ch][0],A[1][ch][1],A[1][ch][2],A[1][ch][3], p2,p3);
                MMA(d[2], A[1][ch][0],A[1][ch][1],A[1][ch][2],A[1][ch][3], r0,r1);
                MMA(d[3], A[1][ch][0],A[1][ch][1],A[1][ch][2],A[1][ch][3], r2,r3);
            }

            // Wo fragments for this k-slice (r = nc*32..nc*32+31)
            u32 bh0a,bh0b,bh1a,bh1b, bl0a,bl0b,bl1a,bl1b;
            LDSM2(bh0a,bh0b, wT + (u32)(nc * 64));
            LDSM2(bh1a,bh1b, wT + (u32)(nc * 64 + 32));
            LDSM2(bl0a,bl0b, wT + (u32)(512 + nc * 64));
            LDSM2(bl1a,bl1b, wT + (u32)(512 + nc * 64 + 32));

            // ---- epilogue in registers: bias, tanh, fp16 split, z-MMA ----
            #pragma unroll
            for (int j = 0; j < 4; ++j) {
                const int lc = nc * 32 + j * 8 + 2 * (lane & 3);
                float2 bp = *(const float2*)&BI[lc];
                d[j][0] = tanhf_fast(d[j][0] + bp.x);
                d[j][1] = tanhf_fast(d[j][1] + bp.y);
                d[j][2] = tanhf_fast(d[j][2] + bp.x);
                d[j][3] = tanhf_fast(d[j][3] + bp.y);
            }
            u32 h[8], l[8];
            #pragma unroll
            for (int j = 0; j < 4; ++j) {
                u32 hp0 = pack2(d[j][0], d[j][1]);
                u32 hp1 = pack2(d[j][2], d[j][3]);
                h[2*j] = hp0; h[2*j+1] = hp1;
                l[2*j]   = pack2(d[j][0] - lo_f(hp0), d[j][1] - hi_f(hp0));
                l[2*j+1] = pack2(d[j][2] - lo_f(hp1), d[j][3] - hi_f(hp1));
            }
            MMA(zacc, h[0],h[1],h[2],h[3], bh0a,bh0b);
            MMA(zacc, h[4],h[5],h[6],h[7], bh1a,bh1b);
            MMA(zacc, l[0],l[1],l[2],l[3], bh0a,bh0b);
            MMA(zacc, l[4],l[5],l[6],l[7], bh1a,bh1b);
            MMA(zacc, h[0],h[1],h[2],h[3], bl0a,bl0b);
            MMA(zacc, h[4],h[5],h[6],h[7], bl1a,bl1b);
        }

        // ---- stage end: z frags -> ZN (or out) ----
        const int c0 = 2 * (lane & 3);
        const int g = 16 * w + (lane >> 2);
        if (s < NSTAGE - 1) {
            *(float2*)&ZN[g * 8 + c0]       = make_float2(zacc[0], zacc[1]);
            *(float2*)&ZN[(g + 8) * 8 + c0] = make_float2(zacc[2], zacc[3]);
            __syncthreads();   // ZN ready; also guards B_sm/WO_sm reuse next stage
        } else {
            float* orow = out + (size_t)(2 * blockIdx.x + (g >> 7)) * 1024;
            *(float2*)&orow[(g & 127) * 8 + c0]       = make_float2(zacc[0], zacc[1]);
            *(float2*)&orow[((g + 8) & 127) * 8 + c0] = make_float2(zacc[2], zacc[3]);
        }
    }
}

extern "C" void kernel_launch(void* const* d_in, const int* in_sizes, int n_in,
                              void* d_out, int out_size)
{
    const float* x  = (const float*)d_in[0];   // [4096, 1024]
    const float* Wi = (const float*)d_in[1];   // [4, 256, 80]
    const float* bi = (const float*)d_in[2];   // [4, 256]
    const float* Wo = (const float*)d_in[3];   // [4, 8, 256]
    float* out = (float*)d_out;                // [4096, 1024]

    cudaFuncSetAttribute(rfm_mma_kernel, cudaFuncAttributeMaxDynamicSharedMemorySize, SMEM_TOTAL);

    build_B_kernel<<<NSTAGE, 256>>>(Wi);
    const int nrows = in_sizes[0] / 1024;
    rfm_mma_kernel<<<nrows / 2, TPB, SMEM_TOTAL>>>(x, bi, Wo, out);
}

// round 8
// speedup vs baseline: 14.0845x; 1.3141x over previous
#include <cuda_runtime.h>
#include <cuda_fp16.h>

typedef unsigned int u32;
typedef unsigned short u16;

// LocalDeepRFMFull via mma.sync m16n8k16 fp16 (plain sm_103 PTX).
// 2 batch rows/CTA, 16 warps, m16 tile/warp. Single-pass fp16 main GEMM
// (Ah*Bh; residual ~2^-11 from both A and B rounding), 3-pass fp16-split
// z-GEMM for output accuracy. A-fragments in registers; H never in smem.

#define TPB       512
#define NSTAGE    4
#define A_STRIDE  176               // 80 fp16 cols + pad -> 11 x 16B (conflict-free ldmatrix)
#define A_BYTES   (256*A_STRIDE)    // 45056
#define B_STRIDE  176               // 80 fp16 cols + pad
#define B_BYTES   (256*B_STRIDE)    // 45056
#define WO_STRIDE 1040              // 512 fp16 cols + pad -> 65 x 16B
#define WO_BYTES  (8*WO_STRIDE)     // 8320
#define SMEM_TOTAL (A_BYTES + B_BYTES + WO_BYTES + 2048*4 + 256*4)  // 107648

// Prebuilt fp16 Wi image (cols 0..79), row stride 176B.
__device__ __align__(16) unsigned char g_Bimg[NSTAGE][B_BYTES];

__device__ __forceinline__ u32 smem_u32(const void* p) {
    u32 a;
    asm("{ .reg .u64 t; cvta.to.shared.u64 t, %1; cvt.u32.u64 %0, t; }" : "=r"(a) : "l"(p));
    return a;
}
// pack: low half = fp16(lo), high half = fp16(hi)
__device__ __forceinline__ u32 pack2(float lo, float hi) {
    __half2 h = __floats2half2_rn(lo, hi);
    return *(u32*)&h;
}
__device__ __forceinline__ float lo_f(u32 p) { return __low2float(*(__half2*)&p); }
__device__ __forceinline__ float hi_f(u32 p) { return __high2float(*(__half2*)&p); }
__device__ __forceinline__ float tanhf_fast(float x) {
    float y; asm("tanh.approx.f32 %0, %1;" : "=f"(y) : "f"(x)); return y;
}

#define LDSM4(R0,R1,R2,R3,ADDR) \
    asm volatile("ldmatrix.sync.aligned.m8n8.x4.shared.b16 {%0,%1,%2,%3}, [%4];" \
        : "=r"(R0),"=r"(R1),"=r"(R2),"=r"(R3) : "r"(ADDR))
#define LDSM2(R0,R1,ADDR) \
    asm volatile("ldmatrix.sync.aligned.m8n8.x2.shared.b16 {%0,%1}, [%2];" \
        : "=r"(R0),"=r"(R1) : "r"(ADDR))
#define MMA(D,A0,A1,A2,A3,B0,B1) \
    asm volatile("mma.sync.aligned.m16n8k16.row.col.f32.f16.f16.f32 " \
        "{%0,%1,%2,%3}, {%4,%5,%6,%7}, {%8,%9}, {%0,%1,%2,%3};" \
        : "+f"((D)[0]),"+f"((D)[1]),"+f"((D)[2]),"+f"((D)[3]) \
        : "r"(A0),"r"(A1),"r"(A2),"r"(A3),"r"(B0),"r"(B1))

// ---------------- precompute: fp16 Wi image ----------------
__global__ void build_B_kernel(const float* __restrict__ Wi) {
    const int s = blockIdx.x, r = threadIdx.x;
    const float* w = Wi + (size_t)(s * 256 + r) * 80;
    unsigned char* img = g_Bimg[s] + r * B_STRIDE;
    for (int c = 0; c < 80; c += 2)
        *(u32*)(img + 2 * c) = pack2(w[c], w[c + 1]);
}

// ---------------- main kernel ----------------
__global__ void __launch_bounds__(TPB, 1)
rfm_mma_kernel(const float* __restrict__ x, const float* __restrict__ bi,
               const float* __restrict__ Wo, float* __restrict__ out)
{
    extern __shared__ __align__(16) unsigned char smem[];
    unsigned char* A_sm  = smem;                       // 256 x 80 fp16: xh(40)|zh(40)
    unsigned char* B_sm  = smem + A_BYTES;             // 256 x 80 fp16: Wi hi
    unsigned char* WO_sm = smem + A_BYTES + B_BYTES;   // 8 x 512 fp16: Wo hi(256)|lo(256)
    float* ZN = (float*)(WO_sm + WO_BYTES);            // [2][1024] fp32 z
    float* BI = ZN + 2048;                             // [256]

    const int t = threadIdx.x, w = t >> 5, lane = t & 31;
    const int rr = lane & 7, q = lane >> 3;

    const u32 A32 = smem_u32(A_sm), B32 = smem_u32(B_sm), W32 = smem_u32(WO_sm);

    // m16 tile per warp: rows 16w..16w+15
    const u32 aT = A32 + (u32)((16 * w + rr + 8 * (q & 1)) * A_STRIDE + (q >> 1) * 16);
    const u32 bT = B32 + (u32)((rr + 8 * (q >> 1)) * B_STRIDE + (q & 1) * 16);
    const u32 wT = W32 + (u32)(rr * WO_STRIDE + (q & 1) * 16);

    // ---- init A: x window -> xh cols 0..39 AND zh cols 40..79 (z starts = x) ----
    const float* xrow0 = x + (size_t)(2 * blockIdx.x) * 1024;
    for (int idx = t; idx < 256 * 20; idx += TPB) {
        int g = idx / 20, p = idx - g * 20;
        const float* xr = xrow0 + (g >> 7) * 1024;
        int basei = (8 * (g & 127) - 16 + 2 * p) & 1023;  // even -> pair never wraps
        u32 hp = pack2(xr[basei], xr[basei + 1]);
        unsigned char* arow = A_sm + g * A_STRIDE;
        *(u32*)(arow + 4 * p)      = hp;   // x hi
        *(u32*)(arow + 80 + 4 * p) = hp;   // z hi
    }

    for (int s = 0; s < NSTAGE; ++s) {
        // B image copy (L2-resident across CTAs)
        {
            const uint4* src = (const uint4*)(&g_Bimg[s][0]);
            uint4* dst = (uint4*)B_sm;
            for (int i = t; i < B_BYTES / 16; i += TPB) dst[i] = src[i];
        }
        // Wo split (fp16 hi + lo): hi at byte 2r, lo at 512+2r (row = c)
        for (int idx = t; idx < 2048; idx += TPB) {
            int c = idx >> 8, r = idx & 255;
            float f = Wo[(size_t)s * 2048 + c * 256 + r];
            __half hh = __float2half_rn(f);
            float l = f - __half2float(hh);
            __half hl = __float2half_rn(l);
            *(u16*)(WO_sm + c * WO_STRIDE + 2 * r)       = *(u16*)&hh;
            *(u16*)(WO_sm + c * WO_STRIDE + 512 + 2 * r) = *(u16*)&hl;
        }
        if (t < 256) BI[t] = bi[s * 256 + t];
        // A z-cols from ZN (stages 1..3)
        if (s > 0) {
            for (int idx = t; idx < 256 * 20; idx += TPB) {
                int g = idx / 20, p = idx - g * 20;
                const float* zr = ZN + (g >> 7) * 1024;
                int basei = (8 * (g & 127) - 16 + 2 * p) & 1023;
                u32 hp = pack2(zr[basei], zr[basei + 1]);
                *(u32*)(A_sm + g * A_STRIDE + 80 + 4 * p) = hp;
            }
        }
        __syncthreads();

        // ---- hoist A fragments: 5 k16-chunks = 20 regs ----
        u32 A[5][4];
        #pragma unroll
        for (int ch = 0; ch < 5; ++ch)
            LDSM4(A[ch][0], A[ch][1], A[ch][2], A[ch][3], aT + (u32)(ch * 32));

        float zacc[4] = {0, 0, 0, 0};

        for (int nc = 0; nc < 8; ++nc) {
            float d[4][4] = {};
            const u32 bBase = bT + (u32)(nc * 32 * B_STRIDE);

            // 5 k16-chunks, single pass (Ah*Bh)
            #pragma unroll
            for (int ch = 0; ch < 5; ++ch) {
                u32 p0,p1,p2,p3, r0,r1,r2,r3;
                LDSM4(p0,p1,p2,p3, bBase + ch * 32);
                LDSM4(r0,r1,r2,r3, bBase + 16 * B_STRIDE + ch * 32);
                MMA(d[0], A[ch][0],A[ch][1],A[ch][2],A[ch][3], p0,p1);
                MMA(d[1], A[ch][0],A[ch][1],A[ch][2],A[ch][3], p2,p3);
                MMA(d[2], A[ch][0],A[ch][1],A[ch][2],A[ch][3], r0,r1);
                MMA(d[3], A[ch][0],A[ch][1],A[ch][2],A[ch][3], r2,r3);
            }

            // Wo fragments for this k-slice (r = nc*32..nc*32+31)
            u32 bh0a,bh0b,bh1a,bh1b, bl0a,bl0b,bl1a,bl1b;
            LDSM2(bh0a,bh0b, wT + (u32)(nc * 64));
            LDSM2(bh1a,bh1b, wT + (u32)(nc * 64 + 32));
            LDSM2(bl0a,bl0b, wT + (u32)(512 + nc * 64));
            LDSM2(bl1a,bl1b, wT + (u32)(512 + nc * 64 + 32));

            // ---- epilogue in registers: bias, tanh, fp16 split, z-MMA (3-pass) ----
            #pragma unroll
            for (int j = 0; j < 4; ++j) {
                const int lc = nc * 32 + j * 8 + 2 * (lane & 3);
                float2 bp = *(const float2*)&BI[lc];
                d[j][0] = tanhf_fast(d[j][0] + bp.x);
                d[j][1] = tanhf_fast(d[j][1] + bp.y);
                d[j][2] = tanhf_fast(d[j][2] + bp.x);
                d[j][3] = tanhf_fast(d[j][3] + bp.y);
            }
            u32 h[8], l[8];
            #pragma unroll
            for (int j = 0; j < 4; ++j) {
                u32 hp0 = pack2(d[j][0], d[j][1]);
                u32 hp1 = pack2(d[j][2], d[j][3]);
                h[2*j] = hp0; h[2*j+1] = hp1;
                l[2*j]   = pack2(d[j][0] - lo_f(hp0), d[j][1] - hi_f(hp0));
                l[2*j+1] = pack2(d[j][2] - lo_f(hp1), d[j][3] - hi_f(hp1));
            }
            MMA(zacc, h[0],h[1],h[2],h[3], bh0a,bh0b);
            MMA(zacc, h[4],h[5],h[6],h[7], bh1a,bh1b);
            MMA(zacc, l[0],l[1],l[2],l[3], bh0a,bh0b);
            MMA(zacc, l[4],l[5],l[6],l[7], bh1a,bh1b);
            MMA(zacc, h[0],h[1],h[2],h[3], bl0a,bl0b);
            MMA(zacc, h[4],h[5],h[6],h[7], bl1a,bl1b);
        }

        // ---- stage end: z frags -> ZN (or out) ----
        const int c0 = 2 * (lane & 3);
        const int g = 16 * w + (lane >> 2);
        if (s < NSTAGE - 1) {
            *(float2*)&ZN[g * 8 + c0]       = make_float2(zacc[0], zacc[1]);
            *(float2*)&ZN[(g + 8) * 8 + c0] = make_float2(zacc[2], zacc[3]);
            __syncthreads();   // ZN ready; also guards B_sm/WO_sm reuse next stage
        } else {
            float* orow = out + (size_t)(2 * blockIdx.x + (g >> 7)) * 1024;
            *(float2*)&orow[(g & 127) * 8 + c0]       = make_float2(zacc[0], zacc[1]);
            *(float2*)&orow[((g + 8) & 127) * 8 + c0] = make_float2(zacc[2], zacc[3]);
        }
    }
}

extern "C" void kernel_launch(void* const* d_in, const int* in_sizes, int n_in,
                              void* d_out, int out_size)
{
    const float* x  = (const float*)d_in[0];   // [4096, 1024]
    const float* Wi = (const float*)d_in[1];   // [4, 256, 80]
    const float* bi = (const float*)d_in[2];   // [4, 256]
    const float* Wo = (const float*)d_in[3];   // [4, 8, 256]
    float* out = (float*)d_out;                // [4096, 1024]

    cudaFuncSetAttribute(rfm_mma_kernel, cudaFuncAttributeMaxDynamicSharedMemorySize, SMEM_TOTAL);

    build_B_kernel<<<NSTAGE, 256>>>(Wi);
    const int nrows = in_sizes[0] / 1024;
    rfm_mma_kernel<<<nrows / 2, TPB, SMEM_TOTAL>>>(x, bi, Wo, out);
}

// round 9
// speedup vs baseline: 15.0624x; 1.0694x over previous
#include <cuda_runtime.h>
#include <cuda_fp16.h>

typedef unsigned int u32;
typedef unsigned short u16;

// LocalDeepRFMFull via mma.sync m16n8k16 fp16 (plain sm_103 PTX).
// 2 batch rows/CTA, 16 warps, m16 tile/warp. Single-pass fp16 main GEMM
// (Ah*Bh), 2-pass z-GEMM (h*Woh + h*Wol = h*Wo). B fragments double-buffered
// at k-chunk granularity (software pipeline); A-frags hoisted in registers;
// H never touches smem.

#define TPB       512
#define NSTAGE    4
#define A_STRIDE  176               // 80 fp16 cols + pad -> 11 x 16B (conflict-free ldmatrix)
#define A_BYTES   (256*A_STRIDE)    // 45056
#define B_STRIDE  176
#define B_BYTES   (256*B_STRIDE)    // 45056
#define WO_STRIDE 1040              // 512 fp16 cols + pad -> 65 x 16B
#define WO_BYTES  (8*WO_STRIDE)     // 8320
#define SMEM_TOTAL (A_BYTES + B_BYTES + WO_BYTES + 2048*4 + 256*4)  // 107648

// Prebuilt fp16 Wi image (cols 0..79), row stride 176B.
__device__ __align__(16) unsigned char g_Bimg[NSTAGE][B_BYTES];

__device__ __forceinline__ u32 smem_u32(const void* p) {
    u32 a;
    asm("{ .reg .u64 t; cvta.to.shared.u64 t, %1; cvt.u32.u64 %0, t; }" : "=r"(a) : "l"(p));
    return a;
}
// pack: low half = fp16(lo), high half = fp16(hi)
__device__ __forceinline__ u32 pack2(float lo, float hi) {
    __half2 h = __floats2half2_rn(lo, hi);
    return *(u32*)&h;
}
__device__ __forceinline__ float tanhf_fast(float x) {
    float y; asm("tanh.approx.f32 %0, %1;" : "=f"(y) : "f"(x)); return y;
}

#define LDSM4(R0,R1,R2,R3,ADDR) \
    asm volatile("ldmatrix.sync.aligned.m8n8.x4.shared.b16 {%0,%1,%2,%3}, [%4];" \
        : "=r"(R0),"=r"(R1),"=r"(R2),"=r"(R3) : "r"(ADDR))
#define LDSM2(R0,R1,ADDR) \
    asm volatile("ldmatrix.sync.aligned.m8n8.x2.shared.b16 {%0,%1}, [%2];" \
        : "=r"(R0),"=r"(R1) : "r"(ADDR))
// non-volatile: pure register function, let ptxas schedule freely
#define MMA(D,A0,A1,A2,A3,B0,B1) \
    asm("mma.sync.aligned.m16n8k16.row.col.f32.f16.f16.f32 " \
        "{%0,%1,%2,%3}, {%4,%5,%6,%7}, {%8,%9}, {%0,%1,%2,%3};" \
        : "+f"((D)[0]),"+f"((D)[1]),"+f"((D)[2]),"+f"((D)[3]) \
        : "r"(A0),"r"(A1),"r"(A2),"r"(A3),"r"(B0),"r"(B1))

// ---------------- precompute: fp16 Wi image ----------------
__global__ void build_B_kernel(const float* __restrict__ Wi) {
    const int s = blockIdx.x, r = threadIdx.x;
    const float* w = Wi + (size_t)(s * 256 + r) * 80;
    unsigned char* img = g_Bimg[s] + r * B_STRIDE;
    for (int c = 0; c < 80; c += 2)
        *(u32*)(img + 2 * c) = pack2(w[c], w[c + 1]);
}

// ---------------- main kernel ----------------
__global__ void __launch_bounds__(TPB, 1)
rfm_mma_kernel(const float* __restrict__ x, const float* __restrict__ bi,
               const float* __restrict__ Wo, float* __restrict__ out)
{
    extern __shared__ __align__(16) unsigned char smem[];
    unsigned char* A_sm  = smem;                       // 256 x 80 fp16: xh(40)|zh(40)
    unsigned char* B_sm  = smem + A_BYTES;             // 256 x 80 fp16: Wi hi
    unsigned char* WO_sm = smem + A_BYTES + B_BYTES;   // 8 x 512 fp16: Wo hi(256)|lo(256)
    float* ZN = (float*)(WO_sm + WO_BYTES);            // [2][1024] fp32 z
    float* BI = ZN + 2048;                             // [256]

    const int t = threadIdx.x, w = t >> 5, lane = t & 31;
    const int rr = lane & 7, q = lane >> 3;

    const u32 A32 = smem_u32(A_sm), B32 = smem_u32(B_sm), W32 = smem_u32(WO_sm);

    // m16 tile per warp: rows 16w..16w+15
    const u32 aT = A32 + (u32)((16 * w + rr + 8 * (q & 1)) * A_STRIDE + (q >> 1) * 16);
    const u32 bT = B32 + (u32)((rr + 8 * (q >> 1)) * B_STRIDE + (q & 1) * 16);
    const u32 wT = W32 + (u32)(rr * WO_STRIDE + (q & 1) * 16);

    // ---- init A: x window -> xh cols 0..39 AND zh cols 40..79 (z starts = x) ----
    const float* xrow0 = x + (size_t)(2 * blockIdx.x) * 1024;
    for (int idx = t; idx < 256 * 20; idx += TPB) {
        int g = idx / 20, p = idx - g * 20;
        const float* xr = xrow0 + (g >> 7) * 1024;
        int basei = (8 * (g & 127) - 16 + 2 * p) & 1023;  // even -> pair never wraps
        u32 hp = pack2(xr[basei], xr[basei + 1]);
        unsigned char* arow = A_sm + g * A_STRIDE;
        *(u32*)(arow + 4 * p)      = hp;   // x hi
        *(u32*)(arow + 80 + 4 * p) = hp;   // z hi
    }

    for (int s = 0; s < NSTAGE; ++s) {
        // B image copy (L2-resident across CTAs)
        {
            const uint4* src = (const uint4*)(&g_Bimg[s][0]);
            uint4* dst = (uint4*)B_sm;
            for (int i = t; i < B_BYTES / 16; i += TPB) dst[i] = src[i];
        }
        // Wo split (fp16 hi + lo): hi at byte 2r, lo at 512+2r (row = c)
        for (int idx = t; idx < 2048; idx += TPB) {
            int c = idx >> 8, r = idx & 255;
            float f = Wo[(size_t)s * 2048 + c * 256 + r];
            __half hh = __float2half_rn(f);
            float l = f - __half2float(hh);
            __half hl = __float2half_rn(l);
            *(u16*)(WO_sm + c * WO_STRIDE + 2 * r)       = *(u16*)&hh;
            *(u16*)(WO_sm + c * WO_STRIDE + 512 + 2 * r) = *(u16*)&hl;
        }
        if (t < 256) BI[t] = bi[s * 256 + t];
        // A z-cols from ZN (stages 1..3)
        if (s > 0) {
            for (int idx = t; idx < 256 * 20; idx += TPB) {
                int g = idx / 20, p = idx - g * 20;
                const float* zr = ZN + (g >> 7) * 1024;
                int basei = (8 * (g & 127) - 16 + 2 * p) & 1023;
                u32 hp = pack2(zr[basei], zr[basei + 1]);
                *(u32*)(A_sm + g * A_STRIDE + 80 + 4 * p) = hp;
            }
        }
        __syncthreads();

        // ---- hoist A fragments: 5 k16-chunks = 20 regs ----
        u32 A[5][4];
        #pragma unroll
        for (int ch = 0; ch < 5; ++ch)
            LDSM4(A[ch][0], A[ch][1], A[ch][2], A[ch][3], aT + (u32)(ch * 32));

        float zh[4] = {0, 0, 0, 0}, zl[4] = {0, 0, 0, 0};

        // ---- software-pipelined main loop: double-buffered B fragments ----
        u32 Bp[2][4], Br[2][4];
        LDSM4(Bp[0][0], Bp[0][1], Bp[0][2], Bp[0][3], bT);
        LDSM4(Br[0][0], Br[0][1], Br[0][2], Br[0][3], bT + 16 * B_STRIDE);

        #pragma unroll
        for (int nc = 0; nc < 8; ++nc) {
            const u32 bBase = bT + (u32)(nc * 32 * B_STRIDE);

            // Wo fragments for this k-slice, issued early
            u32 bh0a,bh0b,bh1a,bh1b, bl0a,bl0b,bl1a,bl1b;
            LDSM2(bh0a,bh0b, wT + (u32)(nc * 64));
            LDSM2(bh1a,bh1b, wT + (u32)(nc * 64 + 32));
            LDSM2(bl0a,bl0b, wT + (u32)(512 + nc * 64));
            LDSM2(bl1a,bl1b, wT + (u32)(512 + nc * 64 + 32));

            float d[4][4] = {};
            #pragma unroll
            for (int ch = 0; ch < 5; ++ch) {
                const int cur = (nc * 5 + ch) & 1, nxt = cur ^ 1;
                // prefetch next chunk (or next nc's chunk0)
                if (ch < 4) {
                    LDSM4(Bp[nxt][0], Bp[nxt][1], Bp[nxt][2], Bp[nxt][3],
                          bBase + (ch + 1) * 32);
                    LDSM4(Br[nxt][0], Br[nxt][1], Br[nxt][2], Br[nxt][3],
                          bBase + 16 * B_STRIDE + (ch + 1) * 32);
                } else if (nc < 7) {
                    LDSM4(Bp[nxt][0], Bp[nxt][1], Bp[nxt][2], Bp[nxt][3],
                          bBase + 32 * B_STRIDE);
                    LDSM4(Br[nxt][0], Br[nxt][1], Br[nxt][2], Br[nxt][3],
                          bBase + 48 * B_STRIDE);
                }
                MMA(d[0], A[ch][0],A[ch][1],A[ch][2],A[ch][3], Bp[cur][0],Bp[cur][1]);
                MMA(d[1], A[ch][0],A[ch][1],A[ch][2],A[ch][3], Bp[cur][2],Bp[cur][3]);
                MMA(d[2], A[ch][0],A[ch][1],A[ch][2],A[ch][3], Br[cur][0],Br[cur][1]);
                MMA(d[3], A[ch][0],A[ch][1],A[ch][2],A[ch][3], Br[cur][2],Br[cur][3]);
            }

            // ---- epilogue in registers: bias, tanh, pack; z = h*Woh + h*Wol ----
            u32 h[8];
            #pragma unroll
            for (int j = 0; j < 4; ++j) {
                const int lc = nc * 32 + j * 8 + 2 * (lane & 3);
                float2 bp = *(const float2*)&BI[lc];
                float h0 = tanhf_fast(d[j][0] + bp.x);
                float h1 = tanhf_fast(d[j][1] + bp.y);
                float h2 = tanhf_fast(d[j][2] + bp.x);
                float h3 = tanhf_fast(d[j][3] + bp.y);
                h[2*j]   = pack2(h0, h1);
                h[2*j+1] = pack2(h2, h3);
            }
            MMA(zh, h[0],h[1],h[2],h[3], bh0a,bh0b);
            MMA(zl, h[0],h[1],h[2],h[3], bl0a,bl0b);
            MMA(zh, h[4],h[5],h[6],h[7], bh1a,bh1b);
            MMA(zl, h[4],h[5],h[6],h[7], bl1a,bl1b);
        }

        // ---- stage end: z frags -> ZN (or out) ----
        const int c0 = 2 * (lane & 3);
        const int g = 16 * w + (lane >> 2);
        float z0 = zh[0] + zl[0], z1 = zh[1] + zl[1];
        float z2 = zh[2] + zl[2], z3 = zh[3] + zl[3];
        if (s < NSTAGE - 1) {
            *(float2*)&ZN[g * 8 + c0]       = make_float2(z0, z1);
            *(float2*)&ZN[(g + 8) * 8 + c0] = make_float2(z2, z3);
            __syncthreads();   // ZN ready; also guards B_sm/WO_sm reuse next stage
        } else {
            float* orow = out + (size_t)(2 * blockIdx.x + (g >> 7)) * 1024;
            *(float2*)&orow[(g & 127) * 8 + c0]       = make_float2(z0, z1);
            *(float2*)&orow[((g + 8) & 127) * 8 + c0] = make_float2(z2, z3);
        }
    }
}

extern "C" void kernel_launch(void* const* d_in, const int* in_sizes, int n_in,
                              void* d_out, int out_size)
{
    const float* x  = (const float*)d_in[0];   // [4096, 1024]
    const float* Wi = (const float*)d_in[1];   // [4, 256, 80]
    const float* bi = (const float*)d_in[2];   // [4, 256]
    const float* Wo = (const float*)d_in[3];   // [4, 8, 256]
    float* out = (float*)d_out;                // [4096, 1024]

    cudaFuncSetAttribute(rfm_mma_kernel, cudaFuncAttributeMaxDynamicSharedMemorySize, SMEM_TOTAL);

    build_B_kernel<<<NSTAGE, 256>>>(Wi);
    const int nrows = in_sizes[0] / 1024;
    rfm_mma_kernel<<<nrows / 2, TPB, SMEM_TOTAL>>>(x, bi, Wo, out);
}